// round 13
// baseline (speedup 1.0000x reference)
#include <cuda_runtime.h>
#include <math.h>
#include <stdint.h>

#define BB 128
#define TT 2048
#define HH 200
#define H4 800
#define NSTEPS 5

// ---------------- scratch globals (no cudaMalloc allowed) ------------------
__device__ float g_qproj[BB * HH];
__device__ float g_hpre[BB * H4];
__device__ float g_scores[BB * TT];
__device__ float g_ctxp[8 * BB * HH];
// duplicated+transposed Ua: g_uad[k*200+h] = {Ua[h][k], Ua[h][k]}
__device__ __align__(16) float2 g_uad[HH * HH];

__device__ __forceinline__ float sigf(float x) { return 1.f / (1.f + expf(-x)); }

__device__ __forceinline__ float warp_reduce(float v) {
#pragma unroll
    for (int m = 16; m > 0; m >>= 1) v += __shfl_xor_sync(0xffffffffu, v, m);
    return v;
}

__device__ __forceinline__ float tanh_fast(float x) {
    float e;
    asm("ex2.approx.f32 %0, %1;" : "=f"(e) : "f"(x * 2.885390081777927f));
    float r;
    asm("rcp.approx.f32 %0, %1;" : "=f"(r) : "f"(e + 1.0f));
    return fmaf(-2.f, r, 1.f);
}

__device__ __forceinline__ uint32_t smem_u32(const void* p) {
    uint32_t a;
    asm("{ .reg .u64 t; cvta.to.shared.u64 t, %1; cvt.u32.u64 %0, t; }" : "=r"(a) : "l"(p));
    return a;
}

// packed fp32x2 FMA (B300 FFMA2 — 2 MACs/lane/instr)
#define FMA2(c, a, b) \
    asm("fma.rn.f32x2 %0, %1, %2, %0;" : "+l"(c) : "l"(a), "l"(b))
#define UNPACK2(lo, hi, p) \
    asm("mov.b64 {%0, %1}, %2;" : "=f"(lo), "=f"(hi) : "l"(p))
#define LDS2U64(a, b, addr) \
    asm("ld.shared.v2.u64 {%0,%1}, [%2];" : "=l"(a), "=l"(b) : "r"(addr))
#define CPASYNC16(dst, src) \
    asm volatile("cp.async.cg.shared.global [%0], [%1], 16;" :: "r"(dst), "l"(src))
#define CPCOMMIT() asm volatile("cp.async.commit_group;" ::: "memory")
#define CPWAIT0() asm volatile("cp.async.wait_group 0;" ::: "memory")

// ---------------------------------------------------------------------------
// KD: no-op alignment kernel (keeps k2 as the 4th launch for ncu capture)
// ---------------------------------------------------------------------------
__global__ void kD_align() {}

// ---------------------------------------------------------------------------
// KP: g_uad[k][h] = {Ua[h][k], Ua[h][k]}  (transpose + duplicate, one-time)
// ---------------------------------------------------------------------------
__global__ void kP_dup_ua(const float* __restrict__ Ua) {
    int i = blockIdx.x * 256 + threadIdx.x;
    if (i >= HH * HH) return;
    int k = i / HH, h = i % HH;
    float v = Ua[h * HH + k];
    g_uad[i] = make_float2(v, v);
}

// ---------------------------------------------------------------------------
// K1: q_proj[b,h] = h0[b]·Wa[h] + ba[h];  h_pre[b,j] = h0[b]·W_hh[j] + b_hh[j]
// ---------------------------------------------------------------------------
__global__ void k1_proj(const float* __restrict__ h0, const float* __restrict__ Wa,
                        const float* __restrict__ ba, const float* __restrict__ Whh,
                        const float* __restrict__ bhh) {
    int b = blockIdx.x, tid = threadIdx.x;
    __shared__ float h0s[HH];
    if (tid < HH) h0s[tid] = h0[b * HH + tid];
    __syncthreads();
    for (int j = tid; j < HH; j += blockDim.x) {
        const float4* w = (const float4*)(Wa + j * HH);
        float s0 = 0.f, s1 = 0.f, s2 = 0.f, s3 = 0.f;
#pragma unroll 5
        for (int k = 0; k < HH / 4; k++) {
            float4 wv = w[k];
            const float* hp = &h0s[k * 4];
            s0 = fmaf(wv.x, hp[0], s0); s1 = fmaf(wv.y, hp[1], s1);
            s2 = fmaf(wv.z, hp[2], s2); s3 = fmaf(wv.w, hp[3], s3);
        }
        g_qproj[b * HH + j] = s0 + s1 + s2 + s3 + ba[j];
    }
    for (int j = tid; j < H4; j += blockDim.x) {
        const float4* w = (const float4*)(Whh + j * HH);
        float s0 = 0.f, s1 = 0.f, s2 = 0.f, s3 = 0.f;
#pragma unroll 5
        for (int k = 0; k < HH / 4; k++) {
            float4 wv = w[k];
            const float* hp = &h0s[k * 4];
            s0 = fmaf(wv.x, hp[0], s0); s1 = fmaf(wv.y, hp[1], s1);
            s2 = fmaf(wv.z, hp[2], s2); s3 = fmaf(wv.w, hp[3], s3);
        }
        g_hpre[b * H4 + j] = s0 + s1 + s2 + s3 + bhh[j];
    }
}

// ---------------------------------------------------------------------------
// K2 v5: packed-fp32 (fma.rn.f32x2) fused scores kernel, 800 threads.
// tid = hg*16 + tg:  hg in [0,50) covers 4 h, tg in [0,16) covers 8 t.
// Warp = 2 hg x 16 tg (uniform). Per thread per k: 2 enc LDS.128 (8 t pairs),
// 2 ua LDS.128 (4 dup'd h), 16 FMA2 -> fma-pipe-bound with 25 warps/SM.
// enc transposed+permuted in SMEM; Ua pre-dup'd, cp.async double-buffered.
// ---------------------------------------------------------------------------
#define S2_ENC   0                        // 200*128*4 = 102400
#define S2_UA    102400                   // 2 bufs x 25k*200h*8B = 80000
#define S2_PART  182400                   // 128*50*4  =  25600
#define S2_QPB   208000                   // 800
#define S2_VAS   208800                   // 800
#define S2_TOTAL 209600
#define UA_BUF   40000                    // bytes per 25-k chunk

__global__ __launch_bounds__(800, 1)
void k2_scores_f2(const float* __restrict__ enc,
                  const float* __restrict__ bua, const float* __restrict__ Va,
                  const float* __restrict__ bva) {
    extern __shared__ char smc[];
    float* enc_T = (float*)smc;
    float* part = (float*)(smc + S2_PART);
    float* qpb = (float*)(smc + S2_QPB);
    float* vas = (float*)(smc + S2_VAS);
    const uint32_t sbase = smem_u32(smc);

    const int b = blockIdx.y;
    const int t0 = blockIdx.x * 128;
    const int tid = threadIdx.x;
    const int hg = tid >> 4, tg = tid & 15;

    // ---- prefetch Ua chunk 0 via cp.async (overlaps with enc staging) ----
    {
        const char* src = (const char*)(g_uad);
        uint32_t dst = sbase + S2_UA;
        for (int i = tid; i < 2500; i += 800)
            CPASYNC16(dst + i * 16, src + i * 16);
        CPCOMMIT();
    }

    // ---- stage enc tile, transposed + row-permuted ----
    {
        const float* ep = enc + (size_t)(b * TT + t0) * HH;
#pragma unroll
        for (int it = 0; it < 8; it++) {
            int idx = tid + it * 800;                 // 6400 = 128t * 50 k4
            int t = idx & 127, c = idx >> 7;          // c = k/4
            float4 v = *(const float4*)(ep + (size_t)t * HH + c * 4);
            int tgg = t >> 3, sub = t & 7;
            int pos = ((sub >> 2) << 6) + (tgg << 2) + (sub & 3);
            float vv[4] = {v.x, v.y, v.z, v.w};
#pragma unroll
            for (int j = 0; j < 4; j++)
                enc_T[(c * 4 + j) * 128 + pos] = vv[j];
        }
    }
    if (tid < HH) {
        qpb[tid] = g_qproj[b * HH + tid] + bua[tid];
        vas[tid] = Va[tid];
    }

    uint64_t acc[4][4];
#pragma unroll
    for (int p = 0; p < 4; p++)
#pragma unroll
        for (int j = 0; j < 4; j++) acc[p][j] = 0ull;

    const uint32_t ebase = sbase + S2_ENC + tg * 16;

    for (int c = 0; c < 8; c++) {
        CPWAIT0();            // chunk c resident in buf[c&1]
        __syncthreads();
        if (c < 7) {          // prefetch chunk c+1 into buf[(c+1)&1]
            const char* src = (const char*)(g_uad + (c + 1) * 25 * HH);
            uint32_t dst = sbase + S2_UA + ((c + 1) & 1) * UA_BUF;
            for (int i = tid; i < 2500; i += 800)
                CPASYNC16(dst + i * 16, src + i * 16);
            CPCOMMIT();
        }

        const uint32_t ubase = sbase + S2_UA + (c & 1) * UA_BUF + hg * 32;
#pragma unroll
        for (int kk = 0; kk < 25; kk++) {
            uint32_t ea = ebase + (c * 25 + kk) * 512;
            uint32_t ua = ubase + kk * 1600;
            uint64_t E0, E1, E2, E3;
            LDS2U64(E0, E1, ea);
            LDS2U64(E2, E3, ea + 256);
            uint64_t D0, D1, D2, D3;
            LDS2U64(D0, D1, ua);
            LDS2U64(D2, D3, ua + 16);
            FMA2(acc[0][0], E0, D0); FMA2(acc[1][0], E1, D0);
            FMA2(acc[2][0], E2, D0); FMA2(acc[3][0], E3, D0);
            FMA2(acc[0][1], E0, D1); FMA2(acc[1][1], E1, D1);
            FMA2(acc[2][1], E2, D1); FMA2(acc[3][1], E3, D1);
            FMA2(acc[0][2], E0, D2); FMA2(acc[1][2], E1, D2);
            FMA2(acc[2][2], E2, D2); FMA2(acc[3][2], E3, D2);
            FMA2(acc[0][3], E0, D3); FMA2(acc[1][3], E1, D3);
            FMA2(acc[2][3], E2, D3); FMA2(acc[3][3], E3, D3);
        }
        // no trailing sync: next iter's CPWAIT0+syncthreads orders reuse
    }

    // ---- epilogue: tanh + Va partial per t over this thread's 4 h ----
    {
        float sp[8];
#pragma unroll
        for (int s = 0; s < 8; s++) sp[s] = 0.f;
#pragma unroll
        for (int j = 0; j < 4; j++) {
            int h = hg * 4 + j;
            float vq = vas[h], qb = qpb[h];
#pragma unroll
            for (int p = 0; p < 4; p++) {
                float x, y;
                UNPACK2(x, y, acc[p][j]);
                sp[2 * p]     += vq * tanh_fast(x + qb);
                sp[2 * p + 1] += vq * tanh_fast(y + qb);
            }
        }
#pragma unroll
        for (int s = 0; s < 8; s++)
            part[(tg * 8 + s) * 50 + hg] = sp[s];
    }
    __syncthreads();

    if (tid < 128) {
        float s = bva[0];
#pragma unroll
        for (int m = 0; m < 50; m++) s += part[tid * 50 + m];
        g_scores[b * TT + t0 + tid] = s;
    }
}

// ---------------------------------------------------------------------------
// K3a: softmax over T per batch (in-place normalize g_scores)
// ---------------------------------------------------------------------------
__global__ void k3a_softmax() {
    const int b = blockIdx.x, tid = threadIdx.x;
    __shared__ float red[256];

    float lmax = -1e30f;
    for (int t = tid; t < TT; t += 256) lmax = fmaxf(lmax, g_scores[b * TT + t]);
    red[tid] = lmax;
    __syncthreads();
    for (int s = 128; s > 0; s >>= 1) {
        if (tid < s) red[tid] = fmaxf(red[tid], red[tid + s]);
        __syncthreads();
    }
    float smax = red[0];
    __syncthreads();

    float lsum = 0.f;
    for (int t = tid; t < TT; t += 256) lsum += expf(g_scores[b * TT + t] - smax);
    red[tid] = lsum;
    __syncthreads();
    for (int s = 128; s > 0; s >>= 1) {
        if (tid < s) red[tid] += red[tid + s];
        __syncthreads();
    }
    float inv = 1.f / red[0];
    __syncthreads();

    for (int t = tid; t < TT; t += 256)
        g_scores[b * TT + t] = expf(g_scores[b * TT + t] - smax) * inv;
}

// ---------------------------------------------------------------------------
// K3b: context partials (DRAM-bound, ~71% of spec)
// ---------------------------------------------------------------------------
__global__ __launch_bounds__(256)
void k3b_ctx(const float* __restrict__ enc) {
    const int ch = blockIdx.x, b = blockIdx.y, tid = threadIdx.x;
    __shared__ float atts[256];
    __shared__ float pbuf[5 * HH];

    atts[tid] = g_scores[b * TT + ch * 256 + tid];
    __syncthreads();

    const int g = tid % 50, sub = tid / 50;
    if (sub < 5) {
        float4 a = make_float4(0.f, 0.f, 0.f, 0.f);
        const float* base = enc + (size_t)(b * TT + ch * 256) * HH + g * 4;
        for (int t = sub; t < 256; t += 5) {
            float w = atts[t];
            float4 e = *(const float4*)(base + (size_t)t * HH);
            a.x = fmaf(w, e.x, a.x); a.y = fmaf(w, e.y, a.y);
            a.z = fmaf(w, e.z, a.z); a.w = fmaf(w, e.w, a.w);
        }
        *(float4*)&pbuf[sub * HH + g * 4] = a;
    }
    __syncthreads();

    if (tid < HH) {
        float s = 0.f;
#pragma unroll
        for (int u = 0; u < 5; u++) s += pbuf[u * HH + tid];
        g_ctxp[(ch * BB + b) * HH + tid] = s;
    }
}

// ---------------------------------------------------------------------------
// K4: decode (SMEM weights + warp-cooperative matvecs)
// ---------------------------------------------------------------------------
__global__ __launch_bounds__(256)
void k4_decode(const float* __restrict__ x0, const float* __restrict__ c0,
               const float* __restrict__ W_ih, const float* __restrict__ b_ih,
               const float* __restrict__ W1, const float* __restrict__ b1,
               const float* __restrict__ W2, const float* __restrict__ b2,
               const float* __restrict__ W3, const float* __restrict__ b3,
               float* __restrict__ out) {
    extern __shared__ float sm4[];
    float* W1s = sm4;              // 20000
    float* W2s = sm4 + 20000;      // 5000
    float* W3s = sm4 + 25000;      // 50
    float* ctx_s = sm4 + 25056;    // 200
    float* gbase = sm4 + 25256;    // 800
    float* hbuf = sm4 + 26056;     // 200
    float* o1 = sm4 + 26256;       // 104
    float* o2 = sm4 + 26360;       // 56
    float* xsp = sm4 + 26416;      // 1

    const int b = blockIdx.x, tid = threadIdx.x;
    const int w = tid >> 5, lane = tid & 31;

    {
        const float4* s1 = (const float4*)W1;
        float4* d1 = (float4*)W1s;
        for (int i = tid; i < 5000; i += 256) d1[i] = s1[i];
        const float4* s2 = (const float4*)W2;
        float4* d2 = (float4*)W2s;
        for (int i = tid; i < 1250; i += 256) d2[i] = s2[i];
        if (tid < 50) W3s[tid] = W3[tid];
    }
    if (tid < HH) {
        float s = 0.f;
#pragma unroll
        for (int c = 0; c < 8; c++) s += g_ctxp[(c * BB + b) * HH + tid];
        ctx_s[tid] = s;
    }
    if (tid == 0) xsp[0] = x0[b];
    __syncthreads();

    for (int j = tid; j < H4; j += 256) {
        const float* wr = W_ih + (size_t)j * 201 + 1;
        float s0 = 0.f, s1 = 0.f, s2 = 0.f, s3 = 0.f;
#pragma unroll 8
        for (int k = 0; k < HH; k += 4) {
            s0 = fmaf(wr[k], ctx_s[k], s0);
            s1 = fmaf(wr[k + 1], ctx_s[k + 1], s1);
            s2 = fmaf(wr[k + 2], ctx_s[k + 2], s2);
            s3 = fmaf(wr[k + 3], ctx_s[k + 3], s3);
        }
        gbase[j] = s0 + s1 + s2 + s3 + b_ih[j] + g_hpre[b * H4 + j];
    }
    __syncthreads();

    for (int step = 0; step < NSTEPS; step++) {
        float x = xsp[0];
        if (tid < HH) {
            int h = tid;
            float gi = gbase[h]       + x * W_ih[(size_t)h * 201];
            float gf = gbase[200 + h] + x * W_ih[(size_t)(200 + h) * 201];
            float gg = gbase[400 + h] + x * W_ih[(size_t)(400 + h) * 201];
            float go = gbase[600 + h] + x * W_ih[(size_t)(600 + h) * 201];
            float c_new = sigf(gf) * c0[b * HH + h] + sigf(gi) * tanhf(gg);
            hbuf[h] = fmaxf(sigf(go) * tanhf(c_new), 0.f);
        }
        __syncthreads();

        for (int o = w; o < 100; o += 8) {
            float s = 0.f;
            const float* wr = W1s + o * HH;
            for (int k = lane; k < HH; k += 32) s = fmaf(wr[k], hbuf[k], s);
            s = warp_reduce(s);
            if (lane == 0) o1[o] = fmaxf(s + b1[o], 0.f);
        }
        __syncthreads();

        for (int o = w; o < 50; o += 8) {
            float s = 0.f;
            const float* wr = W2s + o * 100;
            for (int k = lane; k < 100; k += 32) s = fmaf(wr[k], o1[k], s);
            s = warp_reduce(s);
            if (lane == 0) o2[o] = fmaxf(s + b2[o], 0.f);
        }
        __syncthreads();

        if (w == 0) {
            float s = 0.f;
            for (int k = lane; k < 50; k += 32) s = fmaf(W3s[k], o2[k], s);
            s = warp_reduce(s);
            if (lane == 0) {
                float y = s + b3[0];
                out[b * NSTEPS + step] = y;
                xsp[0] = y;
            }
        }
        __syncthreads();
    }
}

// ---------------------------------------------------------------------------
extern "C" void kernel_launch(void* const* d_in, const int* in_sizes, int n_in,
                              void* d_out, int out_size) {
    const float* x    = (const float*)d_in[0];
    const float* h0   = (const float*)d_in[1];
    const float* c0   = (const float*)d_in[2];
    const float* enc  = (const float*)d_in[3];
    const float* Wa   = (const float*)d_in[4];
    const float* ba   = (const float*)d_in[5];
    const float* Ua   = (const float*)d_in[6];
    const float* bua  = (const float*)d_in[7];
    const float* Va   = (const float*)d_in[8];
    const float* bva  = (const float*)d_in[9];
    const float* W_ih = (const float*)d_in[10];
    const float* W_hh = (const float*)d_in[11];
    const float* b_ih = (const float*)d_in[12];
    const float* b_hh = (const float*)d_in[13];
    const float* W1   = (const float*)d_in[14];
    const float* b1   = (const float*)d_in[15];
    const float* W2   = (const float*)d_in[16];
    const float* b2   = (const float*)d_in[17];
    const float* W3   = (const float*)d_in[18];
    const float* b3   = (const float*)d_in[19];
    float* out = (float*)d_out;

    cudaFuncSetAttribute(k2_scores_f2, cudaFuncAttributeMaxDynamicSharedMemorySize, S2_TOTAL);
    const int smem4 = 26420 * sizeof(float);
    cudaFuncSetAttribute(k4_decode, cudaFuncAttributeMaxDynamicSharedMemorySize, smem4);

    // launch order arranged so k2 is the 4th launch (ncu captures launch #4)
    kP_dup_ua<<<(HH * HH + 255) / 256, 256>>>(Ua);          // 1
    k1_proj<<<BB, 256>>>(h0, Wa, ba, W_hh, b_hh);           // 2
    kD_align<<<1, 32>>>();                                  // 3 (no-op)
    k2_scores_f2<<<dim3(TT / 128, BB), 800, S2_TOTAL>>>(enc, bua, Va, bva);  // 4
    k3a_softmax<<<BB, 256>>>();                             // 5
    k3b_ctx<<<dim3(8, BB), 256>>>(enc);                     // 6
    k4_decode<<<BB, 256, smem4>>>(x, c0, W_ih, b_ih, W1, b1, W2, b2, W3, b3, out);  // 7
}